// round 10
// baseline (speedup 1.0000x reference)
#include <cuda_runtime.h>
#include <cuda_fp16.h>
#include <cstdint>
#include <math.h>

// x: [B, I, K] = [32, 2048, 16]
// W: [1, I, J, D, K] = [1, 2048, 64, 32, 16]
// v: [B, J, D] = [32, 64, 32]
#define BB   32
#define II   2048
#define KK   16
#define JJ   64
#define DD   32
#define JD   (JJ * DD)        // 2048
#define NCHUNK 32
#define IPC  (II / NCHUNK)    // 64
#define RR   4                // rows per pipeline step
#define STEPS (IPC / RR)      // 16
#define SCI  256              // i's per superchunk
#define NSC  (II / SCI)       // 8 superchunks
#define CHPSC (SCI / IPC)     // 4 chunks per superchunk

__device__ __half g_uhat[(size_t)II * BB * JD];     // [i][b][p] fp16 (256 MB)
__device__ float  g_spart[BB * NCHUNK * JD];        // [b][chunk][p] fp32
__device__ float  g_v[BB * JD];                     // current v
__device__ float  g_vsum[BB * JD];                  // v0 + v1 (logit linearity)

// ---------------- cp.async helpers ----------------
__device__ __forceinline__ void cp_async16(void* smem_ptr, const void* gptr) {
    unsigned int saddr = (unsigned int)__cvta_generic_to_shared(smem_ptr);
    asm volatile("cp.async.cg.shared.global [%0], [%1], 16;\n" :: "r"(saddr), "l"(gptr));
}
__device__ __forceinline__ void cp_commit() {
    asm volatile("cp.async.commit_group;\n" ::: "memory");
}
template <int N>
__device__ __forceinline__ void cp_wait() {
    asm volatile("cp.async.wait_group %0;\n" :: "n"(N) : "memory");
}

// ---------------- packed f32x2 helpers ----------------
__device__ __forceinline__ unsigned long long f32x2_mul(unsigned long long a,
                                                        unsigned long long b) {
    unsigned long long d;
    asm("mul.rn.f32x2 %0, %1, %2;" : "=l"(d) : "l"(a), "l"(b));
    return d;
}
__device__ __forceinline__ unsigned long long f32x2_fma(unsigned long long a,
                                                        unsigned long long b,
                                                        unsigned long long c) {
    unsigned long long d;
    asm("fma.rn.f32x2 %0, %1, %2, %3;" : "=l"(d) : "l"(a), "l"(b), "l"(c));
    return d;
}
__device__ __forceinline__ float f32x2_hsum(unsigned long long a) {
    float lo, hi;
    asm("mov.b64 {%0, %1}, %2;" : "=f"(lo), "=f"(hi) : "l"(a));
    return lo + hi;
}

// ---------------------------------------------------------------------------
// K1: u_hat[i][b][p] = sum_k W[i, p, k] * x[b, i, k], fp16 output.
// One CTA per i (offset by i0). W streamed with __ldcs so the freshly
// written u_hat superchunk stays in L2 for the paired k_pass0.
// ---------------------------------------------------------------------------
__global__ void __launch_bounds__(256) k_uhat(const float* __restrict__ x,
                                              const float* __restrict__ W,
                                              int i0) {
    const int i   = i0 + blockIdx.x;
    const int tid = threadIdx.x;

    __shared__ ulonglong2 xs2[BB * 4];   // x[:, i, :], 16B chunks (f32x2 pairs)
    if (tid < BB * 4) {
        const int b = tid >> 2, k4 = tid & 3;
        xs2[tid] = reinterpret_cast<const ulonglong2*>(x)[(size_t)b * (II * 4) + (size_t)i * 4 + k4];
    }
    __syncthreads();

    const uint4* W4 = reinterpret_cast<const uint4*>(W) + (size_t)i * (JD * 4);
    __half* out = g_uhat + (size_t)i * (BB * JD);

    #pragma unroll
    for (int q = 0; q < 2; ++q) {
        const int f  = q * 256 + tid;   // group of 4 p's, f in [0,512)
        const int p0 = f * 4;

        ulonglong2 w2[4][4];
        #pragma unroll
        for (int r = 0; r < 4; ++r)
            #pragma unroll
            for (int c = 0; c < 4; ++c) {
                const uint4 raw = __ldcs(W4 + (size_t)(p0 + r) * 4 + c);
                w2[r][c] = *reinterpret_cast<const ulonglong2*>(&raw);
            }

        #pragma unroll 2
        for (int b = 0; b < BB; ++b) {
            ulonglong2 xv[4];
            #pragma unroll
            for (int c = 0; c < 4; ++c) xv[c] = xs2[b * 4 + c];

            float u[4];
            #pragma unroll
            for (int r = 0; r < 4; ++r) {
                unsigned long long acc = f32x2_mul(w2[r][0].x, xv[0].x);
                acc = f32x2_fma(w2[r][0].y, xv[0].y, acc);
                acc = f32x2_fma(w2[r][1].x, xv[1].x, acc);
                acc = f32x2_fma(w2[r][1].y, xv[1].y, acc);
                acc = f32x2_fma(w2[r][2].x, xv[2].x, acc);
                acc = f32x2_fma(w2[r][2].y, xv[2].y, acc);
                acc = f32x2_fma(w2[r][3].x, xv[3].x, acc);
                acc = f32x2_fma(w2[r][3].y, xv[3].y, acc);
                u[r] = f32x2_hsum(acc);
            }
            __half2 h0 = __floats2half2_rn(u[0], u[1]);
            __half2 h1 = __floats2half2_rn(u[2], u[3]);
            uint2 pack;
            pack.x = *reinterpret_cast<unsigned int*>(&h0);
            pack.y = *reinterpret_cast<unsigned int*>(&h1);
            reinterpret_cast<uint2*>(out + (size_t)b * JD)[f] = pack;
        }
    }
}

// ---------------------------------------------------------------------------
// Pass 0: uniform coefficients — chunk partial sums. fp16 in (hot in L2),
// fp32 out. grid: (CHPSC, B) per superchunk, chunk offset ch0.
// ---------------------------------------------------------------------------
__global__ void __launch_bounds__(256) k_pass0(int ch0) {
    const int ch  = ch0 + blockIdx.x;
    const int b   = blockIdx.y;
    const int tid = threadIdx.x;

    float s[8];
    #pragma unroll
    for (int q = 0; q < 8; ++q) s[q] = 0.f;

    const uint4* base = reinterpret_cast<const uint4*>(
        g_uhat + (size_t)(ch * IPC) * (BB * JD) + (size_t)b * JD);
    const size_t stride = (size_t)BB * JD / 8;

    #pragma unroll 8
    for (int ii = 0; ii < IPC; ++ii) {
        const uint4 raw = base[(size_t)ii * stride + tid];
        const __half2* h = reinterpret_cast<const __half2*>(&raw);
        #pragma unroll
        for (int m = 0; m < 4; ++m) {
            const float2 f = __half22float2(h[m]);
            s[2 * m]     += f.x;
            s[2 * m + 1] += f.y;
        }
    }

    float4* sp = reinterpret_cast<float4*>(g_spart + ((size_t)b * NCHUNK + ch) * JD);
    sp[2 * tid]     = make_float4(s[0], s[1], s[2], s[3]);
    sp[2 * tid + 1] = make_float4(s[4], s[5], s[6], s[7]);
}

// ---------------------------------------------------------------------------
// Passes 1 & 2: register-resident u rows, double-buffered cp.async.
// Agreement logits vs g_v (pass 1) or g_vsum = v0+v1 (pass 2, useVsum=1).
// Thread t owns halves 8t..8t+7 of every row (single j = t>>2).
// grid: (B, NCHUNK), 256 threads.
// ---------------------------------------------------------------------------
__global__ void __launch_bounds__(256, 4) k_pass12(int useVsum) {
    const int b   = blockIdx.x;
    const int ch  = blockIdx.y;
    const int tid = threadIdx.x;
    const int r   = tid >> 6;    // softmax-space row (0..3)
    const int j   = tid & 63;    // softmax-space capsule
    const int wid = tid >> 5;

    __shared__ uint4  ub[2][RR][256];      // 2 x 4 rows x 4KB fp16 (32 KB)
    __shared__ float  lg[JJ * 5];          // [j*5 + rr], padded stride
    __shared__ float  cs[RR][JJ];          // normalized coeffs
    __shared__ float2 ms[8];               // per-warp (max, sum)

    // v in registers: thread t holds vsrc[b, 8t..8t+7]
    const float* vsrc = useVsum ? g_vsum : g_v;   // device-side symbol address: valid
    float vf[8];
    {
        const float4* gv4 = reinterpret_cast<const float4*>(vsrc + (size_t)b * JD);
        const float4 v0 = gv4[2 * tid], v1 = gv4[2 * tid + 1];
        vf[0] = v0.x; vf[1] = v0.y; vf[2] = v0.z; vf[3] = v0.w;
        vf[4] = v1.x; vf[5] = v1.y; vf[6] = v1.z; vf[7] = v1.w;
    }

    float s[8];
    #pragma unroll
    for (int q = 0; q < 8; ++q) s[q] = 0.f;

    const uint4* grow0 = reinterpret_cast<const uint4*>(
        g_uhat + (size_t)(ch * IPC) * (BB * JD) + (size_t)b * JD);
    const size_t gstride = (size_t)BB * JD / 8;   // uint4 per i row

    // prologue: prefetch steps 0 and 1
    #pragma unroll
    for (int rr = 0; rr < RR; ++rr)
        cp_async16(&ub[0][rr][tid], grow0 + (size_t)rr * gstride + tid);
    cp_commit();
    #pragma unroll
    for (int rr = 0; rr < RR; ++rr)
        cp_async16(&ub[1][rr][tid], grow0 + (size_t)(RR + rr) * gstride + tid);
    cp_commit();

    for (int st = 0; st < STEPS; ++st) {
        if (st == STEPS - 1) cp_wait<0>(); else cp_wait<1>();
        const int buf = st & 1;

        // pull this step's u into registers (only own-thread data -> no sync)
        uint4 u4[RR];
        #pragma unroll
        for (int rr = 0; rr < RR; ++rr) u4[rr] = ub[buf][rr][tid];

        // refill this buffer immediately (thread t is sole producer+consumer)
        if (st + 2 < STEPS) {
            const uint4* gr = grow0 + (size_t)(st + 2) * RR * gstride;
            #pragma unroll
            for (int rr = 0; rr < RR; ++rr)
                cp_async16(&ub[buf][rr][tid], gr + (size_t)rr * gstride + tid);
            cp_commit();
        }

        // ---- agreement: per-thread 8-FMA partial dot + quad reduce ----
        float a[RR];
        #pragma unroll
        for (int rr = 0; rr < RR; ++rr) {
            const __half2* h = reinterpret_cast<const __half2*>(&u4[rr]);
            float acc = 0.f;
            #pragma unroll
            for (int m = 0; m < 4; ++m) {
                const float2 f = __half22float2(h[m]);
                acc += f.x * vf[2 * m] + f.y * vf[2 * m + 1];
            }
            acc += __shfl_xor_sync(0xffffffffu, acc, 1);
            acc += __shfl_xor_sync(0xffffffffu, acc, 2);
            a[rr] = acc;
        }
        // thread t publishes row (t&3), capsule (t>>2): conflict-free STS
        lg[(tid >> 2) * 5 + (tid & 3)] = a[tid & 3];
        __syncthreads();

        // ---- softmax in (r, j) space ----
        const float araw = lg[j * 5 + r];

        float mw = araw;
        #pragma unroll
        for (int o = 16; o > 0; o >>= 1)
            mw = fmaxf(mw, __shfl_xor_sync(0xffffffffu, mw, o));
        const float e = __expf(araw - mw);
        float sw = e;
        #pragma unroll
        for (int o = 16; o > 0; o >>= 1)
            sw += __shfl_xor_sync(0xffffffffu, sw, o);
        if ((tid & 31) == 0) ms[wid] = make_float2(mw, sw);
        __syncthreads();
        {
            const float2 other = ms[wid ^ 1];
            const float M = fmaxf(mw, other.x);
            const float S = sw * __expf(mw - M) + other.y * __expf(other.x - M);
            cs[r][j] = e * __expf(mw - M) / S;
        }
        __syncthreads();

        // ---- weighted accumulate from registers ----
        #pragma unroll
        for (int rr = 0; rr < RR; ++rr) {
            const float c = cs[rr][tid >> 2];   // broadcast within quad
            const __half2* h = reinterpret_cast<const __half2*>(&u4[rr]);
            #pragma unroll
            for (int m = 0; m < 4; ++m) {
                const float2 f = __half22float2(h[m]);
                s[2 * m]     += c * f.x;
                s[2 * m + 1] += c * f.y;
            }
        }
    }

    // thread t owns p = 8t..8t+7
    float4* sp = reinterpret_cast<float4*>(g_spart + ((size_t)b * NCHUNK + ch) * JD);
    sp[2 * tid]     = make_float4(s[0], s[1], s[2], s[3]);
    sp[2 * tid + 1] = make_float4(s[4], s[5], s[6], s[7]);
}

// ---------------------------------------------------------------------------
// Squash: one 32-thread block per (b,j).
// mode 0: g_v = v, g_vsum = v        (after iter 0)
// mode 1: g_vsum += v                (after iter 1; pass2 reads g_vsum)
// mode 2: out = v                    (after iter 2)
// ---------------------------------------------------------------------------
__global__ void k_squash(float prescale, int mode, float* __restrict__ out) {
    const int row = blockIdx.x;          // b*64 + j
    const int d   = threadIdx.x;
    const int b   = row >> 6;
    const int j   = row & 63;

    const float* sp = g_spart + (size_t)b * NCHUNK * JD + j * 32 + d;
    float sv = 0.f;
    #pragma unroll 8
    for (int ch = 0; ch < NCHUNK; ++ch) sv += sp[(size_t)ch * JD];
    sv *= prescale;

    float sq = sv * sv;
    #pragma unroll
    for (int o = 16; o > 0; o >>= 1) sq += __shfl_xor_sync(0xffffffffu, sq, o);

    const float scale = sq / (1.f + sq);
    const float v = scale * sv / sqrtf(sq + 1e-8f);

    const int idx = row * 32 + d;
    if (mode == 0)      { g_v[idx] = v; g_vsum[idx] = v; }
    else if (mode == 1) { g_vsum[idx] += v; }
    else                { out[idx] = v; }
}

// ---------------------------------------------------------------------------
extern "C" void kernel_launch(void* const* d_in, const int* in_sizes, int n_in,
                              void* d_out, int out_size) {
    (void)n_in; (void)out_size;
    const float* x = (const float*)d_in[0];
    const float* W = (const float*)d_in[1];
    if (in_sizes[0] > in_sizes[1]) { const float* t = x; x = W; W = t; }

    float* out = (float*)d_out;

    // Interleave u_hat production with pass-0 consumption per 32 MB superchunk
    // so pass-0 reads hit L2 (W is streamed past L2 via __ldcs).
    for (int sc = 0; sc < NSC; ++sc) {
        k_uhat<<<SCI, 256>>>(x, W, sc * SCI);
        k_pass0<<<dim3(CHPSC, BB), 256>>>(sc * CHPSC);
    }
    k_squash<<<BB * JJ, 32>>>(1.0f / 64.0f, 0, nullptr);     // v0 ; vsum = v0

    k_pass12<<<dim3(BB, NCHUNK), 256>>>(0);                  // logits vs v0
    k_squash<<<BB * JJ, 32>>>(1.0f, 1, nullptr);             // vsum = v0+v1

    k_pass12<<<dim3(BB, NCHUNK), 256>>>(1);                  // logits vs v0+v1
    k_squash<<<BB * JJ, 32>>>(1.0f, 2, out);                 // v2 -> d_out
}

// round 11
// speedup vs baseline: 1.2540x; 1.2540x over previous
#include <cuda_runtime.h>
#include <cuda_fp16.h>
#include <cstdint>
#include <math.h>

// x: [B, I, K] = [32, 2048, 16]
// W: [1, I, J, D, K] = [1, 2048, 64, 32, 16]
// v: [B, J, D] = [32, 64, 32]
#define BB   32
#define II   2048
#define KK   16
#define JJ   64
#define DD   32
#define JD   (JJ * DD)        // 2048
#define NCHUNK 32
#define IPC  (II / NCHUNK)    // 64
#define RR   4                // rows per pipeline step
#define STEPS (IPC / RR)      // 16

__device__ __half g_uhat[(size_t)II * BB * JD];     // [i][b][p] fp16 (256 MB)
__device__ float  g_spart[BB * NCHUNK * JD];        // [b][chunk][p] fp32
__device__ float  g_v[BB * JD];                     // current v
__device__ float  g_vsum[BB * JD];                  // v0 + v1 (logit linearity)

// ---------------- cp.async helpers ----------------
__device__ __forceinline__ void cp_async16(void* smem_ptr, const void* gptr) {
    unsigned int saddr = (unsigned int)__cvta_generic_to_shared(smem_ptr);
    asm volatile("cp.async.cg.shared.global [%0], [%1], 16;\n" :: "r"(saddr), "l"(gptr));
}
__device__ __forceinline__ void cp_commit() {
    asm volatile("cp.async.commit_group;\n" ::: "memory");
}
template <int N>
__device__ __forceinline__ void cp_wait() {
    asm volatile("cp.async.wait_group %0;\n" :: "n"(N) : "memory");
}

// ---------------- packed f32x2 helpers ----------------
__device__ __forceinline__ unsigned long long f32x2_mul(unsigned long long a,
                                                        unsigned long long b) {
    unsigned long long d;
    asm("mul.rn.f32x2 %0, %1, %2;" : "=l"(d) : "l"(a), "l"(b));
    return d;
}
__device__ __forceinline__ unsigned long long f32x2_fma(unsigned long long a,
                                                        unsigned long long b,
                                                        unsigned long long c) {
    unsigned long long d;
    asm("fma.rn.f32x2 %0, %1, %2, %3;" : "=l"(d) : "l"(a), "l"(b), "l"(c));
    return d;
}
__device__ __forceinline__ float f32x2_hsum(unsigned long long a) {
    float lo, hi;
    asm("mov.b64 {%0, %1}, %2;" : "=f"(lo), "=f"(hi) : "l"(a));
    return lo + hi;
}

// ---------------------------------------------------------------------------
// K1: u_hat[i][b][p] = sum_k W[i, p, k] * x[b, i, k], fp16 output.
// One CTA per i, 256 threads, packed f32x2 FMA chain.
// ---------------------------------------------------------------------------
__global__ void __launch_bounds__(256) k_uhat(const float* __restrict__ x,
                                              const float* __restrict__ W) {
    const int i   = blockIdx.x;
    const int tid = threadIdx.x;

    __shared__ ulonglong2 xs2[BB * 4];   // x[:, i, :], 16B chunks (f32x2 pairs)
    if (tid < BB * 4) {
        const int b = tid >> 2, k4 = tid & 3;
        xs2[tid] = reinterpret_cast<const ulonglong2*>(x)[(size_t)b * (II * 4) + (size_t)i * 4 + k4];
    }
    __syncthreads();

    const ulonglong2* W2 = reinterpret_cast<const ulonglong2*>(W) + (size_t)i * (JD * 4);
    __half* out = g_uhat + (size_t)i * (BB * JD);

    #pragma unroll
    for (int q = 0; q < 2; ++q) {
        const int f  = q * 256 + tid;   // group of 4 p's, f in [0,512)
        const int p0 = f * 4;

        ulonglong2 w2[4][4];
        #pragma unroll
        for (int r = 0; r < 4; ++r)
            #pragma unroll
            for (int c = 0; c < 4; ++c)
                w2[r][c] = W2[(size_t)(p0 + r) * 4 + c];

        #pragma unroll 2
        for (int b = 0; b < BB; ++b) {
            ulonglong2 xv[4];
            #pragma unroll
            for (int c = 0; c < 4; ++c) xv[c] = xs2[b * 4 + c];

            float u[4];
            #pragma unroll
            for (int r = 0; r < 4; ++r) {
                unsigned long long acc = f32x2_mul(w2[r][0].x, xv[0].x);
                acc = f32x2_fma(w2[r][0].y, xv[0].y, acc);
                acc = f32x2_fma(w2[r][1].x, xv[1].x, acc);
                acc = f32x2_fma(w2[r][1].y, xv[1].y, acc);
                acc = f32x2_fma(w2[r][2].x, xv[2].x, acc);
                acc = f32x2_fma(w2[r][2].y, xv[2].y, acc);
                acc = f32x2_fma(w2[r][3].x, xv[3].x, acc);
                acc = f32x2_fma(w2[r][3].y, xv[3].y, acc);
                u[r] = f32x2_hsum(acc);
            }
            __half2 h0 = __floats2half2_rn(u[0], u[1]);
            __half2 h1 = __floats2half2_rn(u[2], u[3]);
            uint2 pack;
            pack.x = *reinterpret_cast<unsigned int*>(&h0);
            pack.y = *reinterpret_cast<unsigned int*>(&h1);
            reinterpret_cast<uint2*>(out + (size_t)b * JD)[f] = pack;
        }
    }
}

// ---------------------------------------------------------------------------
// Pass 0: uniform coefficients — chunk partial sums. fp16 in, fp32 out.
// grid: (NCHUNK, B), 256 threads.
// ---------------------------------------------------------------------------
__global__ void __launch_bounds__(256) k_pass0() {
    const int ch  = blockIdx.x;
    const int b   = blockIdx.y;
    const int tid = threadIdx.x;

    float s[8];
    #pragma unroll
    for (int q = 0; q < 8; ++q) s[q] = 0.f;

    const uint4* base = reinterpret_cast<const uint4*>(
        g_uhat + (size_t)(ch * IPC) * (BB * JD) + (size_t)b * JD);
    const size_t stride = (size_t)BB * JD / 8;

    #pragma unroll 8
    for (int ii = 0; ii < IPC; ++ii) {
        const uint4 raw = base[(size_t)ii * stride + tid];
        const __half2* h = reinterpret_cast<const __half2*>(&raw);
        #pragma unroll
        for (int m = 0; m < 4; ++m) {
            const float2 f = __half22float2(h[m]);
            s[2 * m]     += f.x;
            s[2 * m + 1] += f.y;
        }
    }

    float4* sp = reinterpret_cast<float4*>(g_spart + ((size_t)b * NCHUNK + ch) * JD);
    sp[2 * tid]     = make_float4(s[0], s[1], s[2], s[3]);
    sp[2 * tid + 1] = make_float4(s[4], s[5], s[6], s[7]);
}

// ---------------------------------------------------------------------------
// Passes 1 & 2: register-resident u rows, double-buffered cp.async.
// Agreement logits vs g_v (pass 1) or g_vsum = v0+v1 (pass 2, useVsum=1).
// Thread t owns halves 8t..8t+7 of every row (single j = t>>2).
// grid: (B, NCHUNK), 256 threads.
// ---------------------------------------------------------------------------
__global__ void __launch_bounds__(256, 4) k_pass12(int useVsum) {
    const int b   = blockIdx.x;
    const int ch  = blockIdx.y;
    const int tid = threadIdx.x;
    const int r   = tid >> 6;    // softmax-space row (0..3)
    const int j   = tid & 63;    // softmax-space capsule
    const int wid = tid >> 5;

    __shared__ uint4  ub[2][RR][256];      // 2 x 4 rows x 4KB fp16 (32 KB)
    __shared__ float  lg[JJ * 5];          // [j*5 + rr], padded stride
    __shared__ float  cs[RR][JJ];          // normalized coeffs
    __shared__ float2 ms[8];               // per-warp (max, sum)

    // v in registers: thread t holds vsrc[b, 8t..8t+7]
    const float* vsrc = useVsum ? g_vsum : g_v;   // device-side symbol address
    float vf[8];
    {
        const float4* gv4 = reinterpret_cast<const float4*>(vsrc + (size_t)b * JD);
        const float4 v0 = gv4[2 * tid], v1 = gv4[2 * tid + 1];
        vf[0] = v0.x; vf[1] = v0.y; vf[2] = v0.z; vf[3] = v0.w;
        vf[4] = v1.x; vf[5] = v1.y; vf[6] = v1.z; vf[7] = v1.w;
    }

    float s[8];
    #pragma unroll
    for (int q = 0; q < 8; ++q) s[q] = 0.f;

    const uint4* grow0 = reinterpret_cast<const uint4*>(
        g_uhat + (size_t)(ch * IPC) * (BB * JD) + (size_t)b * JD);
    const size_t gstride = (size_t)BB * JD / 8;   // uint4 per i row

    // prologue: prefetch steps 0 and 1
    #pragma unroll
    for (int rr = 0; rr < RR; ++rr)
        cp_async16(&ub[0][rr][tid], grow0 + (size_t)rr * gstride + tid);
    cp_commit();
    #pragma unroll
    for (int rr = 0; rr < RR; ++rr)
        cp_async16(&ub[1][rr][tid], grow0 + (size_t)(RR + rr) * gstride + tid);
    cp_commit();

    for (int st = 0; st < STEPS; ++st) {
        if (st == STEPS - 1) cp_wait<0>(); else cp_wait<1>();
        const int buf = st & 1;

        // pull this step's u into registers (only own-thread data -> no sync)
        uint4 u4[RR];
        #pragma unroll
        for (int rr = 0; rr < RR; ++rr) u4[rr] = ub[buf][rr][tid];

        // refill this buffer immediately (thread t is sole producer+consumer)
        if (st + 2 < STEPS) {
            const uint4* gr = grow0 + (size_t)(st + 2) * RR * gstride;
            #pragma unroll
            for (int rr = 0; rr < RR; ++rr)
                cp_async16(&ub[buf][rr][tid], gr + (size_t)rr * gstride + tid);
            cp_commit();
        }

        // ---- agreement: per-thread 8-FMA partial dot + quad reduce ----
        float a[RR];
        #pragma unroll
        for (int rr = 0; rr < RR; ++rr) {
            const __half2* h = reinterpret_cast<const __half2*>(&u4[rr]);
            float acc = 0.f;
            #pragma unroll
            for (int m = 0; m < 4; ++m) {
                const float2 f = __half22float2(h[m]);
                acc += f.x * vf[2 * m] + f.y * vf[2 * m + 1];
            }
            acc += __shfl_xor_sync(0xffffffffu, acc, 1);
            acc += __shfl_xor_sync(0xffffffffu, acc, 2);
            a[rr] = acc;
        }
        // thread t publishes row (t&3), capsule (t>>2): conflict-free STS
        lg[(tid >> 2) * 5 + (tid & 3)] = a[tid & 3];
        __syncthreads();

        // ---- softmax in (r, j) space ----
        const float araw = lg[j * 5 + r];

        float mw = araw;
        #pragma unroll
        for (int o = 16; o > 0; o >>= 1)
            mw = fmaxf(mw, __shfl_xor_sync(0xffffffffu, mw, o));
        const float e = __expf(araw - mw);
        float sw = e;
        #pragma unroll
        for (int o = 16; o > 0; o >>= 1)
            sw += __shfl_xor_sync(0xffffffffu, sw, o);
        if ((tid & 31) == 0) ms[wid] = make_float2(mw, sw);
        __syncthreads();
        {
            const float2 other = ms[wid ^ 1];
            const float M = fmaxf(mw, other.x);
            const float S = sw * __expf(mw - M) + other.y * __expf(other.x - M);
            cs[r][j] = e * __expf(mw - M) / S;
        }
        __syncthreads();

        // ---- weighted accumulate from registers ----
        #pragma unroll
        for (int rr = 0; rr < RR; ++rr) {
            const float c = cs[rr][tid >> 2];   // broadcast within quad
            const __half2* h = reinterpret_cast<const __half2*>(&u4[rr]);
            #pragma unroll
            for (int m = 0; m < 4; ++m) {
                const float2 f = __half22float2(h[m]);
                s[2 * m]     += c * f.x;
                s[2 * m + 1] += c * f.y;
            }
        }
    }

    // thread t owns p = 8t..8t+7
    float4* sp = reinterpret_cast<float4*>(g_spart + ((size_t)b * NCHUNK + ch) * JD);
    sp[2 * tid]     = make_float4(s[0], s[1], s[2], s[3]);
    sp[2 * tid + 1] = make_float4(s[4], s[5], s[6], s[7]);
}

// ---------------------------------------------------------------------------
// Squash: one 32-thread block per (b,j).
// mode 0: g_v = v, g_vsum = v        (after iter 0)
// mode 1: g_vsum += v                (after iter 1; pass2 reads g_vsum)
// mode 2: out = v                    (after iter 2)
// ---------------------------------------------------------------------------
__global__ void k_squash(float prescale, int mode, float* __restrict__ out) {
    const int row = blockIdx.x;          // b*64 + j
    const int d   = threadIdx.x;
    const int b   = row >> 6;
    const int j   = row & 63;

    const float* sp = g_spart + (size_t)b * NCHUNK * JD + j * 32 + d;
    float sv = 0.f;
    #pragma unroll 8
    for (int ch = 0; ch < NCHUNK; ++ch) sv += sp[(size_t)ch * JD];
    sv *= prescale;

    float sq = sv * sv;
    #pragma unroll
    for (int o = 16; o > 0; o >>= 1) sq += __shfl_xor_sync(0xffffffffu, sq, o);

    const float scale = sq / (1.f + sq);
    const float v = scale * sv / sqrtf(sq + 1e-8f);

    const int idx = row * 32 + d;
    if (mode == 0)      { g_v[idx] = v; g_vsum[idx] = v; }
    else if (mode == 1) { g_vsum[idx] += v; }
    else                { out[idx] = v; }
}

// ---------------------------------------------------------------------------
extern "C" void kernel_launch(void* const* d_in, const int* in_sizes, int n_in,
                              void* d_out, int out_size) {
    (void)n_in; (void)out_size;
    const float* x = (const float*)d_in[0];
    const float* W = (const float*)d_in[1];
    if (in_sizes[0] > in_sizes[1]) { const float* t = x; x = W; W = t; }

    float* out = (float*)d_out;

    k_uhat<<<II, 256>>>(x, W);

    k_pass0<<<dim3(NCHUNK, BB), 256>>>();
    k_squash<<<BB * JJ, 32>>>(1.0f / 64.0f, 0, nullptr);     // v0 ; vsum = v0

    k_pass12<<<dim3(BB, NCHUNK), 256>>>(0);                  // logits vs v0
    k_squash<<<BB * JJ, 32>>>(1.0f, 1, nullptr);             // vsum = v0+v1

    k_pass12<<<dim3(BB, NCHUNK), 256>>>(1);                  // logits vs v0+v1
    k_squash<<<BB * JJ, 32>>>(1.0f, 2, out);                 // v2 -> d_out
}